// round 4
// baseline (speedup 1.0000x reference)
#include <cuda_runtime.h>
#include <cstdint>

// ---------------------------------------------------------------------------
// OutputLayer_53798760349842: HeteroConv of two NNConv(out=1) relations
//   out[i] = sum_{e: dst_h2i=i} x_house[src_e]  · (W_edge_h2i @ ea_e + b_h2i)
//          + sum_{e: dst_i2i=i} x_indivi[src_e] · (W_edge_i2i @ ea_e + b_i2i)
//          + x_indivi[i] · (W_root_h2i + W_root_i2i) + bias_h2i + bias_i2i
//
// Plan: 3 launches.
//   1) root_kernel writes the dense root term into out (also initializes the
//      poisoned output buffer).
//   2,3) edge_kernel<F> : one thread per edge; per-edge weight vector
//      w = W@ea+b computed with packed f32x2 FMAs (sm_10x FFMA2), message
//      msg = x_src[src]·w, scatter-added into out with atomicAdd.
// ---------------------------------------------------------------------------

// ---- packed f32x2 helpers (sm_103a FFMA2; PTX-only encoding) --------------
__device__ __forceinline__ unsigned long long pack2f(float lo, float hi) {
    unsigned long long r;
    asm("mov.b64 %0, {%1, %2};" : "=l"(r) : "f"(lo), "f"(hi));
    return r;
}
__device__ __forceinline__ unsigned long long pack2u(unsigned lo, unsigned hi) {
    unsigned long long r;
    asm("mov.b64 %0, {%1, %2};" : "=l"(r) : "r"(lo), "r"(hi));
    return r;
}
__device__ __forceinline__ unsigned long long fma2(unsigned long long a,
                                                   unsigned long long b,
                                                   unsigned long long c) {
    unsigned long long d;
    asm("fma.rn.f32x2 %0, %1, %2, %3;" : "=l"(d) : "l"(a), "l"(b), "l"(c));
    return d;
}
__device__ __forceinline__ float hsum2(unsigned long long v) {
    unsigned lo, hi;
    asm("mov.b64 {%0, %1}, %2;" : "=r"(lo), "=r"(hi) : "l"(v));
    return __uint_as_float(lo) + __uint_as_float(hi);
}

// ---------------------------------------------------------------------------
// Kernel 1: root transform  out[i] = x_indivi[i] . (Wr1+Wr2) + b1 + b2
// Each thread consumes one full 128B row (one full cache line) -> full BW.
// ---------------------------------------------------------------------------
__global__ __launch_bounds__(256)
void root_kernel(const float* __restrict__ x_indivi,
                 const float* __restrict__ Wr1,
                 const float* __restrict__ b1,
                 const float* __restrict__ Wr2,
                 const float* __restrict__ b2,
                 float* __restrict__ out, int n) {
    __shared__ float wr[32];
    __shared__ float bias;
    if (threadIdx.x < 32) wr[threadIdx.x] = Wr1[threadIdx.x] + Wr2[threadIdx.x];
    if (threadIdx.x == 0) bias = b1[0] + b2[0];
    __syncthreads();
    int i = blockIdx.x * blockDim.x + threadIdx.x;
    if (i >= n) return;
    const float4* xr = reinterpret_cast<const float4*>(x_indivi + (size_t)i * 32);
    float acc = bias;
#pragma unroll
    for (int j = 0; j < 8; j++) {
        float4 v = __ldg(xr + j);
        acc = fmaf(v.x, wr[j * 4 + 0],
              fmaf(v.y, wr[j * 4 + 1],
              fmaf(v.z, wr[j * 4 + 2],
              fmaf(v.w, wr[j * 4 + 3], acc))));
    }
    out[i] = acc;
}

// ---------------------------------------------------------------------------
// Kernel 2/3: edge message + scatter-add, one thread per edge.
//   W: [F, 8] row-major.  msg = sum_f x_src[src][f] * (sum_k W[f][k]*ea[k] + b[f])
// Weights pre-paired into f32x2 in shared (broadcast LDS, conflict-free).
// Per-thread loads: 32B edge_attr (coalesced float4 x2), F*4B gather (uint4,
// L2-resident table), 8B indices. FFMA2 halves scalar FMA count.
// ---------------------------------------------------------------------------
template <int F>
__global__ __launch_bounds__(256)
void edge_kernel(const float* __restrict__ x_src,
                 const float* __restrict__ ea,
                 const int* __restrict__ src,
                 const int* __restrict__ dst,
                 const float* __restrict__ W,
                 const float* __restrict__ b,
                 float* __restrict__ out, int E) {
    constexpr int NP = F / 2;  // f32x2 pairs along feature dim
    __shared__ unsigned long long sW2[NP * 8];
    __shared__ unsigned long long sb2[NP];
    int t = threadIdx.x;
    if (t < NP * 8) {
        int p = t >> 3, k = t & 7;
        sW2[t] = pack2f(W[(2 * p) * 8 + k], W[(2 * p + 1) * 8 + k]);
    }
    if (t < NP) sb2[t] = pack2f(b[2 * t], b[2 * t + 1]);
    __syncthreads();

    int e = blockIdx.x * blockDim.x + t;
    if (e >= E) return;

    // edge_attr: 8 floats per edge, 32B-aligned -> two coalesced float4 loads
    const float4* eap = reinterpret_cast<const float4*>(ea + (size_t)e * 8);
    float4 a0 = __ldg(eap);
    float4 a1 = __ldg(eap + 1);
    unsigned long long ap[8];
    ap[0] = pack2f(a0.x, a0.x);  ap[1] = pack2f(a0.y, a0.y);
    ap[2] = pack2f(a0.z, a0.z);  ap[3] = pack2f(a0.w, a0.w);
    ap[4] = pack2f(a1.x, a1.x);  ap[5] = pack2f(a1.y, a1.y);
    ap[6] = pack2f(a1.z, a1.z);  ap[7] = pack2f(a1.w, a1.w);

    int s = __ldg(src + e);
    const uint4* xr = reinterpret_cast<const uint4*>(x_src + (size_t)s * F);

    unsigned long long msg2 = pack2f(0.0f, 0.0f);
#pragma unroll
    for (int j = 0; j < F / 4; j++) {
        uint4 xv = __ldg(xr + j);  // gather: L2-resident feature table
        unsigned long long x01 = pack2u(xv.x, xv.y);
        unsigned long long x23 = pack2u(xv.z, xv.w);
        int p0 = 2 * j, p1 = 2 * j + 1;
        unsigned long long w0 = sb2[p0];
        unsigned long long w1 = sb2[p1];
#pragma unroll
        for (int k = 0; k < 8; k++) {
            w0 = fma2(sW2[p0 * 8 + k], ap[k], w0);
            w1 = fma2(sW2[p1 * 8 + k], ap[k], w1);
        }
        msg2 = fma2(x01, w0, msg2);
        msg2 = fma2(x23, w1, msg2);
    }
    float msg = hsum2(msg2);
    atomicAdd(out + __ldg(dst + e), msg);
}

// ---------------------------------------------------------------------------
extern "C" void kernel_launch(void* const* d_in, const int* in_sizes, int n_in,
                              void* d_out, int out_size) {
    const float* x_indivi  = (const float*)d_in[0];
    const float* x_house   = (const float*)d_in[1];
    const float* ea_h2i    = (const float*)d_in[2];
    const float* ea_i2i    = (const float*)d_in[3];
    const float* W_e_h2i   = (const float*)d_in[4];
    const float* b_e_h2i   = (const float*)d_in[5];
    const float* W_e_i2i   = (const float*)d_in[6];
    const float* b_e_i2i   = (const float*)d_in[7];
    const float* W_r_h2i   = (const float*)d_in[8];
    const float* bias_h2i  = (const float*)d_in[9];
    const float* W_r_i2i   = (const float*)d_in[10];
    const float* bias_i2i  = (const float*)d_in[11];
    const int*   src_h2i   = (const int*)d_in[12];
    const int*   dst_h2i   = (const int*)d_in[13];
    const int*   src_i2i   = (const int*)d_in[14];
    const int*   dst_i2i   = (const int*)d_in[15];
    float* out = (float*)d_out;

    const int nI = out_size;       // 500000
    const int E1 = in_sizes[12];   // 2000000
    const int E2 = in_sizes[14];   // 2000000

    const int T = 256;
    root_kernel<<<(nI + T - 1) / T, T>>>(x_indivi, W_r_h2i, bias_h2i,
                                         W_r_i2i, bias_i2i, out, nI);
    edge_kernel<16><<<(E1 + T - 1) / T, T>>>(x_house, ea_h2i, src_h2i, dst_h2i,
                                             W_e_h2i, b_e_h2i, out, E1);
    edge_kernel<32><<<(E2 + T - 1) / T, T>>>(x_indivi, ea_i2i, src_i2i, dst_i2i,
                                             W_e_i2i, b_e_i2i, out, E2);
}